// round 4
// baseline (speedup 1.0000x reference)
#include <cuda_runtime.h>

#define IMG_H 256
#define IMG_W 256
#define NPIX (8 * IMG_H * IMG_W)
#define NVOX 1000000

// Packed texel: depth float with mask bit stolen into mantissa LSB.
// Tiled layout: idx = (b<<16) | ((v>>3)<<11) | ((u>>3)<<6) | ((v&7)<<3) | (u&7)
// -> one 8x8 pixel tile = 256B = 2 cache lines.
__device__ unsigned g_md[NPIX];

// Vectorized pack: each thread handles 4 consecutive pixels (same tile row ->
// 4 consecutive texels -> one uint4 store).
__global__ void pack_md_kernel(const float4* __restrict__ mask4,
                               const float4* __restrict__ depth4) {
    int i = blockIdx.x * blockDim.x + threadIdx.x;     // quad index
    if (i >= NPIX / 4) return;
    float4 m = mask4[i];
    float4 d = depth4[i];
    uint4 o;
    o.x = (__float_as_uint(d.x) & ~1u) | (m.x != 0.0f ? 1u : 0u);
    o.y = (__float_as_uint(d.y) & ~1u) | (m.y != 0.0f ? 1u : 0u);
    o.z = (__float_as_uint(d.z) & ~1u) | (m.z != 0.0f ? 1u : 0u);
    o.w = (__float_as_uint(d.w) & ~1u) | (m.w != 0.0f ? 1u : 0u);
    int p   = i << 2;                // first pixel id
    int b   = p >> 16;
    int rem = p & 0xFFFF;
    int v   = rem >> 8;
    int u   = rem & 0xFF;
    int dst = (b << 16) | ((v >> 3) << 11) | ((u >> 3) << 6) | ((v & 7) << 3) | (u & 7);
    *reinterpret_cast<uint4*>(&g_md[dst]) = o;
}

// 8 lanes per voxel: lane = vertex. Warp = 4 voxels -> one gather LDG touches
// only ~4 small footprints instead of 32 uncorrelated pixels.
__global__ __launch_bounds__(256) void octree_kernel(
    const float* __restrict__ pts,
    const float* __restrict__ Km,
    const int*   __restrict__ bids,
    const float* __restrict__ gsz,
    float2*      __restrict__ out)
{
    int t    = blockIdx.x * blockDim.x + threadIdx.x;  // 8M threads exactly
    int vox  = t >> 3;
    int vert = t & 7;

    float px = __ldg(&pts[3 * vox + 0]);
    float py = __ldg(&pts[3 * vox + 1]);
    float pz = __ldg(&pts[3 * vox + 2]);
    int   bid = __ldg(&bids[vox]);

    float gs = gsz[0];
    float fx = Km[0], cx = Km[2];
    float fy = Km[4], cy = Km[5];
    float h  = 0.5f * gs;

    // GRID_OFFSET sign masks: x + for verts {1,2,5,6}=0x66, y + for {2,3,6,7}=0xCC,
    // z + for verts >= 4.
    float x = px + (((0x66 >> vert) & 1) ? h : -h);
    float y = py + (((0xCC >> vert) & 1) ? h : -h);
    float z = pz + ((vert & 4) ? h : -h);
    z = fmaxf(z, 1e-6f);

    // Bit-exact match to JAX: mul, then rn-division, then add.
    float u = __fdiv_rn(fx * x, z) + cx;
    float v = __fdiv_rn(fy * y, z) + cy;

    int pu = min(max(__float2int_rn(u), 0), IMG_W - 1);
    int pv = min(max(__float2int_rn(v), 0), IMG_H - 1);

    int idx = (bid << 16) | ((pv >> 3) << 11) | ((pu >> 3) << 6)
            | ((pv & 7) << 3) | (pu & 7);

    unsigned md = __ldg(&g_md[idx]);

    float d = __uint_as_float(md & ~1u);
    // w * sigmoid((d - z)/tau) = w / (1 + exp((z - d) * 20))
    float e  = __expf((z - d) * 20.0f);
    float w  = (vert & 1) ? 4.0f : 5.0f;
    float fr = __fdividef(w, 1.0f + e);

    // width-8 sum of free contributions
    fr += __shfl_xor_sync(0xFFFFFFFFu, fr, 1);
    fr += __shfl_xor_sync(0xFFFFFFFFu, fr, 2);
    fr += __shfl_xor_sync(0xFFFFFFFFu, fr, 4);

    // cover: exact integer via ballot. weight 5 on even verts, 4 on odd:
    // cover = 4*popc(m8) + popc(m8 & 0x55)
    unsigned bal = __ballot_sync(0xFFFFFFFFu, (md & 1u) != 0u);

    if (vert == 0) {
        unsigned sub = (bal >> (threadIdx.x & 24)) & 0xFFu;
        int cover = 4 * __popc(sub) + __popc(sub & 0x55u);
        const float inv36 = 1.0f / 36.0f;
        out[vox] = make_float2((float)cover * inv36, fr * inv36);
    }
}

extern "C" void kernel_launch(void* const* d_in, const int* in_sizes, int n_in,
                              void* d_out, int out_size) {
    const float* pts   = (const float*)d_in[0];
    const float* mask  = (const float*)d_in[1];
    const float* depth = (const float*)d_in[2];
    const float* Km    = (const float*)d_in[3];
    const int*   bids  = (const int*)  d_in[4];
    const float* gsz   = (const float*)d_in[5];
    float2*      out   = (float2*)d_out;

    pack_md_kernel<<<(NPIX / 4 + 255) / 256, 256>>>(
        (const float4*)mask, (const float4*)depth);
    octree_kernel<<<(NVOX * 8) / 256, 256>>>(pts, Km, bids, gsz, out);
}

// round 5
// speedup vs baseline: 1.5651x; 1.5651x over previous
#include <cuda_runtime.h>

#define IMG_H 256
#define IMG_W 256
#define NPIX (8 * IMG_H * IMG_W)
#define NVOX 1000000

// Packed texel: depth float with mask bit stolen into mantissa LSB.
// Tiled layout: idx = (b<<16) | ((v>>3)<<11) | ((u>>3)<<6) | ((v&7)<<3) | (u&7)
// -> one 8x8 pixel tile = 256B = 2 cache lines.
__device__ unsigned g_md[NPIX];

// Vectorized pack: each thread handles 4 consecutive pixels (same tile row ->
// 4 consecutive texels -> one uint4 store).
__global__ void pack_md_kernel(const float4* __restrict__ mask4,
                               const float4* __restrict__ depth4) {
    int i = blockIdx.x * blockDim.x + threadIdx.x;     // quad index
    if (i >= NPIX / 4) return;
    float4 m = mask4[i];
    float4 d = depth4[i];
    uint4 o;
    o.x = (__float_as_uint(d.x) & ~1u) | (m.x != 0.0f ? 1u : 0u);
    o.y = (__float_as_uint(d.y) & ~1u) | (m.y != 0.0f ? 1u : 0u);
    o.z = (__float_as_uint(d.z) & ~1u) | (m.z != 0.0f ? 1u : 0u);
    o.w = (__float_as_uint(d.w) & ~1u) | (m.w != 0.0f ? 1u : 0u);
    int p   = i << 2;                // first pixel id
    int b   = p >> 16;
    int rem = p & 0xFFFF;
    int v   = rem >> 8;
    int u   = rem & 0xFF;
    int dst = (b << 16) | ((v >> 3) << 11) | ((u >> 3) << 6) | ((v & 7) << 3) | (u & 7);
    *reinterpret_cast<uint4*>(&g_md[dst]) = o;
}

__device__ __forceinline__ int texel_idx(int base, int pu, int pv) {
    return base | ((pv >> 3) << 11) | ((pu >> 3) << 6) | ((pv & 7) << 3) | (pu & 7);
}

// 2 lanes per voxel (lane pair = z-plane). Compute per voxel same as the
// 1-thread version (4 rn-divides + 4 sigmoids per thread), but a warp's
// gather LDG covers only 16 voxel footprints -> ~half the L1 wavefronts.
__global__ __launch_bounds__(256) void octree_kernel(
    const float* __restrict__ pts,
    const float* __restrict__ Km,
    const int*   __restrict__ bids,
    const float* __restrict__ gsz,
    float2*      __restrict__ out)
{
    int t = blockIdx.x * blockDim.x + threadIdx.x;
    if (t >= 2 * NVOX) return;
    int vox   = t >> 1;
    int plane = t & 1;        // 0: zm (verts 0-3), 1: zp (verts 4-7)

    float px = __ldg(&pts[3 * vox + 0]);
    float py = __ldg(&pts[3 * vox + 1]);
    float pz = __ldg(&pts[3 * vox + 2]);
    int   bid = __ldg(&bids[vox]);

    float gs = gsz[0];
    float fx = Km[0], cx = Km[2];
    float fy = Km[4], cy = Km[5];
    float h  = 0.5f * gs;

    float xm = px - h, xp = px + h;
    float ym = py - h, yp = py + h;
    float z  = fmaxf(plane ? pz + h : pz - h, 1e-6f);

    // Bit-exact vs JAX: (K00*x) rn-divided by z, then + cx.
    float u_m = __fdiv_rn(fx * xm, z) + cx;
    float u_p = __fdiv_rn(fx * xp, z) + cx;
    float v_m = __fdiv_rn(fy * ym, z) + cy;
    float v_p = __fdiv_rn(fy * yp, z) + cy;

    int pu_m = min(max(__float2int_rn(u_m), 0), IMG_W - 1);
    int pu_p = min(max(__float2int_rn(u_p), 0), IMG_W - 1);
    int pv_m = min(max(__float2int_rn(v_m), 0), IMG_H - 1);
    int pv_p = min(max(__float2int_rn(v_p), 0), IMG_H - 1);

    int base = bid << 16;
    // Corner order (both planes): (m,m) w5, (p,m) w4, (p,p) w5, (m,p) w4
    int i0 = texel_idx(base, pu_m, pv_m);
    int i1 = texel_idx(base, pu_p, pv_m);
    int i2 = texel_idx(base, pu_p, pv_p);
    int i3 = texel_idx(base, pu_m, pv_p);

    unsigned m0 = __ldg(&g_md[i0]);
    unsigned m1 = __ldg(&g_md[i1]);
    unsigned m2 = __ldg(&g_md[i2]);
    unsigned m3 = __ldg(&g_md[i3]);

    // cover partial: exact integers
    int cov = 5 * (int)(m0 & 1u) + 4 * (int)(m1 & 1u)
            + 5 * (int)(m2 & 1u) + 4 * (int)(m3 & 1u);

    // free partial: w * sigmoid((d - z)/tau) = w / (1 + exp((z - d) * 20))
    float d0 = __uint_as_float(m0 & ~1u);
    float d1 = __uint_as_float(m1 & ~1u);
    float d2 = __uint_as_float(m2 & ~1u);
    float d3 = __uint_as_float(m3 & ~1u);
    float fr = __fdividef(5.0f, 1.0f + __expf((z - d0) * 20.0f))
             + __fdividef(4.0f, 1.0f + __expf((z - d1) * 20.0f))
             + __fdividef(5.0f, 1.0f + __expf((z - d2) * 20.0f))
             + __fdividef(4.0f, 1.0f + __expf((z - d3) * 20.0f));

    // combine the two z-planes of this voxel
    fr  += __shfl_xor_sync(0xFFFFFFFFu, fr, 1);
    cov += __shfl_xor_sync(0xFFFFFFFFu, cov, 1);

    if (plane == 0) {
        const float inv36 = 1.0f / 36.0f;
        out[vox] = make_float2((float)cov * inv36, fr * inv36);
    }
}

extern "C" void kernel_launch(void* const* d_in, const int* in_sizes, int n_in,
                              void* d_out, int out_size) {
    const float* pts   = (const float*)d_in[0];
    const float* mask  = (const float*)d_in[1];
    const float* depth = (const float*)d_in[2];
    const float* Km    = (const float*)d_in[3];
    const int*   bids  = (const int*)  d_in[4];
    const float* gsz   = (const float*)d_in[5];
    float2*      out   = (float2*)d_out;

    pack_md_kernel<<<(NPIX / 4 + 255) / 256, 256>>>(
        (const float4*)mask, (const float4*)depth);
    octree_kernel<<<(2 * NVOX + 255) / 256, 256>>>(pts, Km, bids, gsz, out);
}

// round 6
// speedup vs baseline: 1.6882x; 1.0787x over previous
#include <cuda_runtime.h>

#define IMG_H 256
#define IMG_W 256
#define NPIX (8 * IMG_H * IMG_W)
#define NVOX 1000000

// Packed texel: depth float with mask bit stolen into mantissa LSB.
// Tiled layout: idx = (b<<16) | ((v>>3)<<11) | ((u>>3)<<6) | ((v&7)<<3) | (u&7)
// -> one 8x8 pixel tile = 256B = 2 cache lines.
__device__ unsigned g_md[NPIX];

__global__ void pack_md_kernel(const float4* __restrict__ mask4,
                               const float4* __restrict__ depth4) {
    int i = blockIdx.x * blockDim.x + threadIdx.x;     // quad index
    if (i >= NPIX / 4) return;
    float4 m = mask4[i];
    float4 d = depth4[i];
    uint4 o;
    o.x = (__float_as_uint(d.x) & ~1u) | (m.x != 0.0f ? 1u : 0u);
    o.y = (__float_as_uint(d.y) & ~1u) | (m.y != 0.0f ? 1u : 0u);
    o.z = (__float_as_uint(d.z) & ~1u) | (m.z != 0.0f ? 1u : 0u);
    o.w = (__float_as_uint(d.w) & ~1u) | (m.w != 0.0f ? 1u : 0u);
    int p   = i << 2;
    int b   = p >> 16;
    int rem = p & 0xFFFF;
    int v   = rem >> 8;
    int u   = rem & 0xFF;
    int dst = (b << 16) | ((v >> 3) << 11) | ((u >> 3) << 6) | ((v & 7) << 3) | (u & 7);
    *reinterpret_cast<uint4*>(&g_md[dst]) = o;
}

__device__ __forceinline__ int upart(int pu) {   // ((pu>>3)<<6) | (pu&7)
    return ((pu & 0xF8) << 3) | (pu & 7);
}
__device__ __forceinline__ int vpart(int pv) {   // ((pv>>3)<<11) | ((pv&7)<<3)
    return ((pv & 0xF8) << 8) | ((pv & 7) << 3);
}

// 2 lanes per voxel (lane = z-plane), 2 voxels per thread for MLP.
// Warp = 16 lane-pairs = 32 voxels; each gather LDG covers 16 voxel
// footprints; 8 gathers are in flight per thread.
__global__ __launch_bounds__(256) void octree_kernel(
    const float* __restrict__ pts,
    const float* __restrict__ Km,
    const int*   __restrict__ bids,
    const float* __restrict__ gsz,
    float4*      __restrict__ out)   // float4 = two adjacent float2 results
{
    int t = blockIdx.x * blockDim.x + threadIdx.x;   // NVOX threads total
    int pairid = t >> 1;
    int plane  = t & 1;          // 0: zm (verts 0-3), 1: zp (verts 4-7)
    if (pairid >= NVOX / 2) return;
    int vox0 = pairid << 1;

    float gs = gsz[0];
    float fx = Km[0], cx = Km[2];
    float fy = Km[4], cy = Km[5];
    float h  = 0.5f * gs;
    float zsign = plane ? h : -h;

    int   idx[2][4];
    float zz[2];

#pragma unroll
    for (int k = 0; k < 2; k++) {
        int vx = vox0 + k;
        float px = __ldg(&pts[3 * vx + 0]);
        float py = __ldg(&pts[3 * vx + 1]);
        float pz = __ldg(&pts[3 * vx + 2]);
        int   base = __ldg(&bids[vx]) << 16;

        float xm = px - h, xp = px + h;
        float ym = py - h, yp = py + h;
        float z  = fmaxf(pz + zsign, 1e-6f);
        zz[k] = z;

        // Bit-exact vs JAX: (K00*x) rn-divided by z, then + cx, then rn-round.
        float u_m = __fdiv_rn(fx * xm, z) + cx;
        float u_p = __fdiv_rn(fx * xp, z) + cx;
        float v_m = __fdiv_rn(fy * ym, z) + cy;
        float v_p = __fdiv_rn(fy * yp, z) + cy;

        int ua = upart(min(max(__float2int_rn(u_m), 0), IMG_W - 1));
        int ub = upart(min(max(__float2int_rn(u_p), 0), IMG_W - 1));
        int va = vpart(min(max(__float2int_rn(v_m), 0), IMG_H - 1));
        int vb = vpart(min(max(__float2int_rn(v_p), 0), IMG_H - 1));

        // Corner order (both planes): (m,m) w5, (p,m) w4, (p,p) w5, (m,p) w4
        idx[k][0] = base | va | ua;
        idx[k][1] = base | va | ub;
        idx[k][2] = base | vb | ub;
        idx[k][3] = base | vb | ua;
    }

    // Issue all 8 gathers before consuming any.
    unsigned md[2][4];
#pragma unroll
    for (int k = 0; k < 2; k++)
#pragma unroll
        for (int c = 0; c < 4; c++) md[k][c] = __ldg(&g_md[idx[k][c]]);

    int   cov01 = 0;
    float fr[2];
#pragma unroll
    for (int k = 0; k < 2; k++) {
        float z = zz[k];
        unsigned m0 = md[k][0], m1 = md[k][1], m2 = md[k][2], m3 = md[k][3];
        int cov = 5 * (int)(m0 & 1u) + 4 * (int)(m1 & 1u)
                + 5 * (int)(m2 & 1u) + 4 * (int)(m3 & 1u);
        cov01 += cov << (16 * k);
        float d0 = __uint_as_float(m0 & ~1u);
        float d1 = __uint_as_float(m1 & ~1u);
        float d2 = __uint_as_float(m2 & ~1u);
        float d3 = __uint_as_float(m3 & ~1u);
        // w * sigmoid((d - z)/tau) = w / (1 + exp((z - d) * 20))
        fr[k] = __fdividef(5.0f, 1.0f + __expf((z - d0) * 20.0f))
              + __fdividef(4.0f, 1.0f + __expf((z - d1) * 20.0f))
              + __fdividef(5.0f, 1.0f + __expf((z - d2) * 20.0f))
              + __fdividef(4.0f, 1.0f + __expf((z - d3) * 20.0f));
    }

    // Combine the two z-planes (lane pair) of both voxels.
    fr[0] += __shfl_xor_sync(0xFFFFFFFFu, fr[0], 1);
    fr[1] += __shfl_xor_sync(0xFFFFFFFFu, fr[1], 1);
    cov01 += __shfl_xor_sync(0xFFFFFFFFu, cov01, 1);

    if (plane == 0) {
        const float inv36 = 1.0f / 36.0f;
        float4 o;
        o.x = (float)(cov01 & 0xFFFF) * inv36;
        o.y = fr[0] * inv36;
        o.z = (float)(cov01 >> 16) * inv36;
        o.w = fr[1] * inv36;
        out[pairid] = o;    // two adjacent float2 results, one 16B store
    }
}

extern "C" void kernel_launch(void* const* d_in, const int* in_sizes, int n_in,
                              void* d_out, int out_size) {
    const float* pts   = (const float*)d_in[0];
    const float* mask  = (const float*)d_in[1];
    const float* depth = (const float*)d_in[2];
    const float* Km    = (const float*)d_in[3];
    const int*   bids  = (const int*)  d_in[4];
    const float* gsz   = (const float*)d_in[5];

    pack_md_kernel<<<(NPIX / 4 + 255) / 256, 256>>>(
        (const float4*)mask, (const float4*)depth);
    octree_kernel<<<(NVOX + 255) / 256, 256>>>(pts, Km, bids, gsz,
                                               (float4*)d_out);
}